// round 16
// baseline (speedup 1.0000x reference)
#include <cuda_runtime.h>

// Problem shapes (fixed by setup_inputs)
#define BB 64
#define TT 1024
#define JJ 32
#define TOTAL (BB * TT * JJ)

// Scratch: per-(b,t) root trajectory, float4-padded. 4 MB.
__device__ float4 d_traj[BB * TT];

// Rotate point p by unit quaternion q=(w,x,y,z): p' = p + w*t + u×t, t = 2*(u×p)
__device__ __forceinline__ void qrotate(float w, float x, float y, float z,
                                        float px, float py, float pz,
                                        float& ox, float& oy, float& oz) {
    float tx = 2.0f * (y * pz - z * py);
    float ty = 2.0f * (z * px - x * pz);
    float tz = 2.0f * (x * py - y * px);
    ox = px + w * tx + (y * tz - z * ty);
    oy = py + w * ty + (z * tx - x * tz);
    oz = pz + w * tz + (x * ty - y * tx);
}

// Kernel 1 (R15 version, measured tail 6.4us): per-batch trajectory scan.
// 64 blocks x 512 threads, 2 t-steps per thread: serial local prefix +
// shfl warp scan + 16-entry smem combine.
__global__ void __launch_bounds__(512)
traj_scan_kernel(const float* __restrict__ glb_pos,
                 const float* __restrict__ glb_vel,
                 const float* __restrict__ root) {
    const int b = blockIdx.x;
    const int tid = threadIdx.x;          // 0..511
    __shared__ float wsx[16], wsy[16], wsz[16];
    const int lane = tid & 31, warp = tid >> 5;

    // e[t] = rot(inv[t-1], vel[t-1, joint0]), e[0] = 0; 2 t-steps per thread
    float ex[2], ey[2], ez[2];
    #pragma unroll
    for (int k = 0; k < 2; k++) {
        int t = tid * 2 + k;
        ex[k] = ey[k] = ez[k] = 0.0f;
        if (t >= 1) {
            int s = t - 1;
            float4 q = __ldg((const float4*)(root + (size_t)(b * TT + s) * 4));
            float4 v = __ldg((const float4*)(glb_vel +
                             (size_t)(b * (TT - 1) + s) * JJ * 3));  // joint0 (+pad)
            qrotate(q.x, -q.y, -q.z, -q.w, v.x, v.y, v.z, ex[k], ey[k], ez[k]);
        }
    }
    ex[1] += ex[0]; ey[1] += ey[0]; ez[1] += ez[0];
    const float thx = ex[1], thy = ey[1], thz = ez[1];

    // warp-inclusive scan of per-thread sums
    float sx = thx, sy = thy, sz = thz;
    #pragma unroll
    for (int d = 1; d < 32; d <<= 1) {
        float nx = __shfl_up_sync(0xffffffffu, sx, d);
        float ny = __shfl_up_sync(0xffffffffu, sy, d);
        float nz = __shfl_up_sync(0xffffffffu, sz, d);
        if (lane >= d) { sx += nx; sy += ny; sz += nz; }
    }
    if (lane == 31) { wsx[warp] = sx; wsy[warp] = sy; wsz[warp] = sz; }
    __syncthreads();
    if (tid == 0) {
        float ax = 0, ay = 0, az = 0;
        #pragma unroll
        for (int w2 = 0; w2 < 16; w2++) {
            float tx = wsx[w2], ty = wsy[w2], tz = wsz[w2];
            wsx[w2] = ax; wsy[w2] = ay; wsz[w2] = az;
            ax += tx; ay += ty; az += tz;
        }
    }
    __syncthreads();

    // base = rot(inv[b,0], pos[b,0,joint0])
    float4 q0 = __ldg((const float4*)(root + (size_t)b * TT * 4));
    float4 p0 = __ldg((const float4*)(glb_pos + (size_t)b * TT * JJ * 3));
    float bx, by, bz;
    qrotate(q0.x, -q0.y, -q0.z, -q0.w, p0.x, p0.y, p0.z, bx, by, bz);

    const float offx = bx + wsx[warp] + (sx - thx);
    const float offy = by + wsy[warp] + (sy - thy);
    const float offz = bz + wsz[warp] + (sz - thz);
    #pragma unroll
    for (int k = 0; k < 2; k++) {
        d_traj[b * TT + tid * 2 + k] =
            make_float4(offx + ex[k], offy + ey[k], offz + ez[k], 0.0f);
    }
}

// Kernel 2 (R13 version, measured 17.4us): elementwise over (b,t,j) —
// 1 element/thread, scalar pos loads (coalesced 32b), float4 rot traffic,
// plain stores.
__global__ void __launch_bounds__(256)
main_kernel(const float* __restrict__ glb_pos,
            const float* __restrict__ glb_rot,
            const float* __restrict__ root,
            float* __restrict__ out) {
    const int idx = blockIdx.x * blockDim.x + threadIdx.x;  // 0 .. TOTAL-1
    const int pair = idx >> 5;  // (b*T + t), since J == 32

    // inv root quaternion (warp-uniform broadcast)
    const float4 q = __ldg((const float4*)(root + (size_t)pair * 4));
    const float w = q.x, x = -q.y, y = -q.z, z = -q.w;

    // --- position path ---
    const float* p = glb_pos + (size_t)idx * 3;
    float px, py, pz;
    qrotate(w, x, y, z, __ldg(p), __ldg(p + 1), __ldg(p + 2), px, py, pz);

    const float4 tr = __ldg(&d_traj[pair]);   // immutable within this kernel

    float* op = out + (size_t)idx * 3;
    op[0] = px + tr.x;
    op[1] = py;
    op[2] = pz + tr.z;

    // --- rotation path: standardize(inv ⊗ glb_rot) ---
    const float4 g = __ldg((const float4*)(glb_rot + (size_t)idx * 4));
    float rw = w * g.x - x * g.y - y * g.z - z * g.w;
    float rx = w * g.y + x * g.x + y * g.w - z * g.z;
    float ry = w * g.z - x * g.w + y * g.x + z * g.y;
    float rz = w * g.w + x * g.z - y * g.y + z * g.x;
    float s = (rw < 0.0f) ? -1.0f : 1.0f;
    ((float4*)(out + (size_t)TOTAL * 3))[idx] =
        make_float4(s * rw, s * rx, s * ry, s * rz);
}

extern "C" void kernel_launch(void* const* d_in, const int* in_sizes, int n_in,
                              void* d_out, int out_size) {
    const float* glb_pos = (const float*)d_in[0];
    const float* glb_rot = (const float*)d_in[1];
    const float* glb_vel = (const float*)d_in[2];
    const float* root    = (const float*)d_in[3];
    float* out = (float*)d_out;

    traj_scan_kernel<<<BB, 512>>>(glb_pos, glb_vel, root);
    main_kernel<<<TOTAL / 256, 256>>>(glb_pos, glb_rot, root, out);
}